// round 10
// baseline (speedup 1.0000x reference)
#include <cuda_runtime.h>
#include <cstdint>

#define D_MODEL 1024
#define HALF    32
#define T_LEN   8192
#define BATCH   4
#define ROWS    (BATCH * T_LEN)   // 32768
#define TAPS    32
#define TT      128
#define RSTR2   40   // u32 stride (16 pairs + pad) -- used by conv/gemm2 tiles

// scratch: projected modes xp[row][n] fp32 (4 MB)
__device__ float g_xp[ROWS * HALF];
// conv output: 16 (hi,lo) bf16x2 pairs per row (4 MB)
__device__ uint2 g_y[ROWS * 16];

// ---------------------------------------------------------------------------
// bf16 helpers
// ---------------------------------------------------------------------------
__device__ __forceinline__ uint32_t pack_bf2(float f0, float f1) {
    uint32_t d;
    asm("cvt.rn.bf16x2.f32 %0, %1, %2;" : "=r"(d) : "f"(f1), "f"(f0));
    return d;
}
__device__ __forceinline__ void split_bf2(float f0, float f1, uint32_t& h, uint32_t& l) {
    h = pack_bf2(f0, f1);
    float f0h = __uint_as_float(h << 16);
    float f1h = __uint_as_float(h & 0xFFFF0000u);
    l = pack_bf2(f0 - f0h, f1 - f1h);
}
__device__ __forceinline__ void mma_bf16(float& c0, float& c1, float& c2, float& c3,
                                         uint32_t a0, uint32_t a1, uint32_t a2, uint32_t a3,
                                         uint32_t b0, uint32_t b1) {
    asm volatile(
        "mma.sync.aligned.m16n8k16.row.col.f32.bf16.bf16.f32 "
        "{%0,%1,%2,%3}, {%4,%5,%6,%7}, {%8,%9}, {%0,%1,%2,%3};"
        : "+f"(c0), "+f"(c1), "+f"(c2), "+f"(c3)
        : "r"(a0), "r"(a1), "r"(a2), "r"(a3), "r"(b0), "r"(b1));
}

// ===========================================================================
// K1: xp[row][n] = sum_d x[row][d]*W_in[n][d]
// bf16x3 split, double-buffered, hi/lo interleaved smem.
// K-stage = 64 columns (32 pairs/row): 16 super-chunks, ONE sync per chunk.
// CTA 128 rows x 32 n, 256 thr. Warp w: rows (w&3)*32..+32, cols (w>>2)*16..+16.
// ===========================================================================
#define K1_AST   72                       // u32 stride per A/B row: 64 data + 8 pad
#define K1_A_U32 (128 * K1_AST)           // 9216
#define K1_B_U32 (32 * K1_AST)            // 2304
#define K1_STAGE (K1_A_U32 + K1_B_U32)    // 11520 u32
#define K1_SMEM_BYTES (2 * K1_STAGE * 4)  // 92160

__global__ void __launch_bounds__(256) proj_mma_kernel(const float* __restrict__ x,
                                                       const float* __restrict__ W_in)
{
    extern __shared__ uint32_t sm1[];
    const int tid = threadIdx.x;
    const int wid = tid >> 5;
    const int lid = tid & 31;
    const int g   = lid >> 2;
    const int tig = lid & 3;
    const int row0 = blockIdx.x * 128;

    const int mroww = (wid & 3) * 32;
    const int ncolw = (wid >> 2) * 16;

    // prefetch registers: A in two 64-row batches, B in one
    float4 pa0[4], pa1[4], pb[2];

    const int lr = tid >> 4;        // 0..15 (row within 16-row group)
    const int lq = tid & 15;        // float4 index within 64-col chunk

    auto ldg_chunk = [&](int c) {
        const int colb = c * 64 + lq * 4;
#pragma unroll
        for (int p = 0; p < 4; p++) {
            const int r = lr + p * 16;          // rows 0..63
            pa0[p] = *(const float4*)(x + (size_t)(row0 + r) * D_MODEL + colb);
        }
#pragma unroll
        for (int p = 0; p < 4; p++) {
            const int r = 64 + lr + p * 16;     // rows 64..127
            pa1[p] = *(const float4*)(x + (size_t)(row0 + r) * D_MODEL + colb);
        }
#pragma unroll
        for (int p = 0; p < 2; p++) {
            const int n = lr + p * 16;          // 0..31
            pb[p] = *(const float4*)(W_in + (size_t)n * D_MODEL + colb);
        }
    };
    auto sts_one = [&](uint32_t* dst, float4 v) {
        uint32_t h0, l0, h1, l1;
        split_bf2(v.x, v.y, h0, l0);
        split_bf2(v.z, v.w, h1, l1);
        *(uint4*)dst = make_uint4(h0, l0, h1, l1);
    };
    auto sts_chunk = [&](int buf) {
        uint32_t* AB = sm1 + buf * K1_STAGE;
        uint32_t* BB = AB + K1_A_U32;
#pragma unroll
        for (int p = 0; p < 4; p++)
            sts_one(&AB[(lr + p * 16) * K1_AST + lq * 4], pa0[p]);
#pragma unroll
        for (int p = 0; p < 4; p++)
            sts_one(&AB[(64 + lr + p * 16) * K1_AST + lq * 4], pa1[p]);
#pragma unroll
        for (int p = 0; p < 2; p++)
            sts_one(&BB[(lr + p * 16) * K1_AST + lq * 4], pb[p]);
    };

    ldg_chunk(0);
    sts_chunk(0);
    ldg_chunk(1);
    __syncthreads();

    float acc[2][2][4];
#pragma unroll
    for (int mt = 0; mt < 2; mt++)
#pragma unroll
        for (int nt = 0; nt < 2; nt++)
#pragma unroll
            for (int i = 0; i < 4; i++) acc[mt][nt][i] = 0.f;

#pragma unroll 1
    for (int c = 0; c < 16; c++) {
        if (c + 1 < 16) sts_chunk((c + 1) & 1);
        if (c + 2 < 16) ldg_chunk(c + 2);

        const uint32_t* AB = sm1 + (c & 1) * K1_STAGE;
        const uint32_t* BB = AB + K1_A_U32;

#pragma unroll
        for (int ks = 0; ks < 4; ks++) {
            const int e0 = ks * 8 + tig;
            uint32_t ah[2][4], al_[2][4];
#pragma unroll
            for (int mt = 0; mt < 2; mt++) {
                const int r = mroww + mt * 16 + g;
                uint2 a00 = *(const uint2*)&AB[r * K1_AST + e0 * 2];
                uint2 a10 = *(const uint2*)&AB[(r + 8) * K1_AST + e0 * 2];
                uint2 a01 = *(const uint2*)&AB[r * K1_AST + (e0 + 4) * 2];
                uint2 a11 = *(const uint2*)&AB[(r + 8) * K1_AST + (e0 + 4) * 2];
                ah[mt][0] = a00.x; al_[mt][0] = a00.y;
                ah[mt][1] = a10.x; al_[mt][1] = a10.y;
                ah[mt][2] = a01.x; al_[mt][2] = a01.y;
                ah[mt][3] = a11.x; al_[mt][3] = a11.y;
            }
            uint32_t bh_[2][2], bl_[2][2];
#pragma unroll
            for (int nt = 0; nt < 2; nt++) {
                const int n = ncolw + nt * 8 + g;
                uint2 b0 = *(const uint2*)&BB[n * K1_AST + e0 * 2];
                uint2 b1 = *(const uint2*)&BB[n * K1_AST + (e0 + 4) * 2];
                bh_[nt][0] = b0.x; bl_[nt][0] = b0.y;
                bh_[nt][1] = b1.x; bl_[nt][1] = b1.y;
            }
#pragma unroll
            for (int mt = 0; mt < 2; mt++)
#pragma unroll
                for (int nt = 0; nt < 2; nt++) {
                    float* cc = acc[mt][nt];
                    mma_bf16(cc[0], cc[1], cc[2], cc[3],
                             ah[mt][0], ah[mt][1], ah[mt][2], ah[mt][3],
                             bh_[nt][0], bh_[nt][1]);
                    mma_bf16(cc[0], cc[1], cc[2], cc[3],
                             ah[mt][0], ah[mt][1], ah[mt][2], ah[mt][3],
                             bl_[nt][0], bl_[nt][1]);
                    mma_bf16(cc[0], cc[1], cc[2], cc[3],
                             al_[mt][0], al_[mt][1], al_[mt][2], al_[mt][3],
                             bh_[nt][0], bh_[nt][1]);
                }
        }
        __syncthreads();
    }

#pragma unroll
    for (int mt = 0; mt < 2; mt++) {
        const int r0 = row0 + mroww + mt * 16 + g;
#pragma unroll
        for (int nt = 0; nt < 2; nt++) {
            const int col = ncolw + nt * 8 + tig * 2;
            *(float2*)(g_xp + (size_t)r0 * HALF + col) =
                make_float2(acc[mt][nt][0], acc[mt][nt][1]);
            *(float2*)(g_xp + (size_t)(r0 + 8) * HALF + col) =
                make_float2(acc[mt][nt][2], acc[mt][nt][3]);
        }
    }
}

// ===========================================================================
// K2: FIR taps + causal conv; writes y as interleaved (hi,lo) uint2. TT=128.
// ===========================================================================
__global__ void __launch_bounds__(256) conv_kernel(
    const float* __restrict__ log_tau, const float* __restrict__ freq,
    const float* __restrict__ Bp,      const float* __restrict__ Cp,
    const float* __restrict__ log_dt)
{
    __shared__ float xp_s[(TT + TAPS - 1) * 32];   // 159 rows
    __shared__ float kk[TAPS][32];
    __shared__ float y_s[TT][32];
    __shared__ float pg[32], pl[32], pa[32];

    const int tid = threadIdx.x;
    const int blk = blockIdx.x;
    const int b   = blk >> 6;              // 64 tiles per batch
    const int t0  = (blk & 63) * TT;

    if (tid < 32) {
        float dt  = expf(log_dt[0]);
        float tau = fmaxf(expf(log_tau[tid]), 1e-4f);
        pl[tid] = -tau * dt;
        pa[tid] = freq[tid] * dt;
        pg[tid] = logf(fabsf(Bp[tid]) + 1e-9f) + logf(fabsf(Cp[tid]) + 1e-9f);
    }

    for (int idx = tid; idx < (TT + TAPS - 1) * 32; idx += 256) {
        const int j = idx >> 5, n = idx & 31;
        const int tq = t0 - (TAPS - 1) + j;
        xp_s[idx] = (tq >= 0) ? g_xp[((size_t)b * T_LEN + tq) * HALF + n] : 0.f;
    }
    __syncthreads();

    for (int idx = tid; idx < TAPS * 32; idx += 256) {
        const int s = idx >> 5, n = idx & 31;
        kk[s][n] = expf(pg[n] + (float)s * pl[n]) * cosf((float)s * pa[n]);
    }
    __syncthreads();

    {
        const int n  = tid & 31;
        const int tg = tid >> 5;
#pragma unroll
        for (int r = 0; r < TT / 8; r++) {
            const int tl = tg * (TT / 8) + r;
            float acc = 0.f;
            const float* base = &xp_s[(tl + TAPS - 1) * 32 + n];
#pragma unroll
            for (int s = 0; s < TAPS; s++) {
                acc += kk[s][n] * base[-s * 32];
            }
            y_s[tl][n] = acc;
        }
    }
    __syncthreads();

    for (int idx = tid; idx < TT * 16; idx += 256) {
        const int t = idx >> 4, kp = idx & 15;
        uint32_t h, l;
        split_bf2(y_s[t][2 * kp], y_s[t][2 * kp + 1], h, l);
        g_y[((size_t)b * T_LEN + t0 + t) * 16 + kp] = make_uint2(h, l);
    }
}

// ===========================================================================
// K3: GEMM2  out[t][d] = sum_n y[t][n] * W_out[d][n]
// bf16x3 split, hi/lo interleaved smem. CTA 128 t x 128 d, grid (256, 8).
// ===========================================================================
#define K3_A_U32      (128 * RSTR2)
#define K3_B_U32      (128 * RSTR2)
#define K3_SMEM_BYTES ((K3_A_U32 + K3_B_U32) * 4)   // 40960

__global__ void __launch_bounds__(256) gemm2_kernel(const float* __restrict__ W_out,
                                                    float* __restrict__ out)
{
    extern __shared__ uint32_t sm3[];
    uint32_t* As = sm3;
    uint32_t* Bs = sm3 + K3_A_U32;

    const int tid = threadIdx.x;
    const int wid = tid >> 5;
    const int lid = tid & 31;
    const int g   = lid >> 2;
    const int tig = lid & 3;

    const int t0 = blockIdx.x * 128;
    const int d0 = blockIdx.y * 128;

#pragma unroll
    for (int p = 0; p < 4; p++) {
        const int f = tid + p * 256;
        const int r = f >> 3, j = f & 7;
        uint4 v = *(const uint4*)&g_y[(size_t)(t0 + r) * 16 + j * 2];
        *(uint4*)&As[r * RSTR2 + j * 4] = v;
    }
#pragma unroll
    for (int p = 0; p < 4; p++) {
        const int f = tid + p * 256;
        const int r = f >> 3, q = f & 7;
        float4 v = *(const float4*)(W_out + (size_t)(d0 + r) * HALF + q * 4);
        uint32_t h0, l0, h1, l1;
        split_bf2(v.x, v.y, h0, l0);
        split_bf2(v.z, v.w, h1, l1);
        *(uint4*)&Bs[r * RSTR2 + q * 4] = make_uint4(h0, l0, h1, l1);
    }
    __syncthreads();

    const int mg = wid & 3;
    const int dg = wid >> 2;

    uint32_t afh[2][2][4], afl[2][2][4];
#pragma unroll
    for (int mt = 0; mt < 2; mt++) {
        const int r = mg * 32 + mt * 16 + g;
#pragma unroll
        for (int ks = 0; ks < 2; ks++) {
            const int e0 = ks * 8 + tig;
            uint2 a00 = *(const uint2*)&As[r * RSTR2 + e0 * 2];
            uint2 a10 = *(const uint2*)&As[(r + 8) * RSTR2 + e0 * 2];
            uint2 a01 = *(const uint2*)&As[r * RSTR2 + (e0 + 4) * 2];
            uint2 a11 = *(const uint2*)&As[(r + 8) * RSTR2 + (e0 + 4) * 2];
            afh[mt][ks][0] = a00.x; afl[mt][ks][0] = a00.y;
            afh[mt][ks][1] = a10.x; afl[mt][ks][1] = a10.y;
            afh[mt][ks][2] = a01.x; afl[mt][ks][2] = a01.y;
            afh[mt][ks][3] = a11.x; afl[mt][ks][3] = a11.y;
        }
    }

#pragma unroll 1
    for (int ch = 0; ch < 8; ch++) {
        const int nb = dg * 64 + ch * 8;
        float acc[2][4];
#pragma unroll
        for (int mt = 0; mt < 2; mt++)
#pragma unroll
            for (int i = 0; i < 4; i++) acc[mt][i] = 0.f;

#pragma unroll
        for (int ks = 0; ks < 2; ks++) {
            const int e0 = ks * 8 + tig;
            const int nr = nb + g;
            uint2 b0 = *(const uint2*)&Bs[nr * RSTR2 + e0 * 2];
            uint2 b1 = *(const uint2*)&Bs[nr * RSTR2 + (e0 + 4) * 2];
            uint32_t bh0 = b0.x, bl0 = b0.y;
            uint32_t bh1 = b1.x, bl1 = b1.y;
#pragma unroll
            for (int mt = 0; mt < 2; mt++) {
                float* cc = acc[mt];
                mma_bf16(cc[0], cc[1], cc[2], cc[3],
                         afh[mt][ks][0], afh[mt][ks][1], afh[mt][ks][2], afh[mt][ks][3],
                         bh0, bh1);
                mma_bf16(cc[0], cc[1], cc[2], cc[3],
                         afh[mt][ks][0], afh[mt][ks][1], afh[mt][ks][2], afh[mt][ks][3],
                         bl0, bl1);
                mma_bf16(cc[0], cc[1], cc[2], cc[3],
                         afl[mt][ks][0], afl[mt][ks][1], afl[mt][ks][2], afl[mt][ks][3],
                         bh0, bh1);
            }
        }

        const int col = d0 + nb + tig * 2;
#pragma unroll
        for (int mt = 0; mt < 2; mt++) {
            const int tr = t0 + mg * 32 + mt * 16 + g;
            *(float2*)(out + (size_t)tr * D_MODEL + col) =
                make_float2(acc[mt][0], acc[mt][1]);
            *(float2*)(out + (size_t)(tr + 8) * D_MODEL + col) =
                make_float2(acc[mt][2], acc[mt][3]);
        }
    }
}

// ---------------------------------------------------------------------------
extern "C" void kernel_launch(void* const* d_in, const int* in_sizes, int n_in,
                              void* d_out, int out_size)
{
    const float* x       = (const float*)d_in[0];
    const float* log_tau = (const float*)d_in[1];
    const float* freq    = (const float*)d_in[2];
    const float* Bp      = (const float*)d_in[3];
    const float* Cp      = (const float*)d_in[4];
    const float* log_dt  = (const float*)d_in[5];
    const float* W_in    = (const float*)d_in[6];
    const float* W_out   = (const float*)d_in[7];
    float* out           = (float*)d_out;

    (void)in_sizes; (void)n_in; (void)out_size;

    static bool attr_set = false;
    if (!attr_set) {
        cudaFuncSetAttribute(proj_mma_kernel,
                             cudaFuncAttributeMaxDynamicSharedMemorySize, K1_SMEM_BYTES);
        cudaFuncSetAttribute(gemm2_kernel,
                             cudaFuncAttributeMaxDynamicSharedMemorySize, K3_SMEM_BYTES);
        attr_set = true;
    }

    proj_mma_kernel<<<ROWS / 128, 256, K1_SMEM_BYTES>>>(x, W_in);
    conv_kernel<<<ROWS / TT, 256>>>(log_tau, freq, Bp, Cp, log_dt);
    gemm2_kernel<<<dim3(ROWS / 128, D_MODEL / 128), 256, K3_SMEM_BYTES>>>(W_out, out);
}

// round 12
// speedup vs baseline: 1.4058x; 1.4058x over previous
#include <cuda_runtime.h>
#include <cstdint>

#define D_MODEL 1024
#define HALF    32
#define T_LEN   8192
#define BATCH   4
#define ROWS    (BATCH * T_LEN)   // 32768
#define TAPS    32
#define TT      64
#define RSTR    20   // u32 stride: 16 data + 4 pad (conflict-free)
#define RSTR2   40   // u32 stride: 16 (hi,lo) pairs + 8 pad

// scratch: projected modes xp[row][n] fp32 (4 MB)
__device__ float g_xp[ROWS * HALF];
// conv output: 16 (hi,lo) bf16x2 pairs per row (4 MB)
__device__ uint2 g_y[ROWS * 16];

// ---------------------------------------------------------------------------
// pack helpers
// ---------------------------------------------------------------------------
__device__ __forceinline__ uint32_t pack_bf2(float f0, float f1) {
    uint32_t d;
    asm("cvt.rn.bf16x2.f32 %0, %1, %2;" : "=r"(d) : "f"(f1), "f"(f0));
    return d;
}
__device__ __forceinline__ void split_bf2(float f0, float f1, uint32_t& h, uint32_t& l) {
    h = pack_bf2(f0, f1);
    float f0h = __uint_as_float(h << 16);
    float f1h = __uint_as_float(h & 0xFFFF0000u);
    l = pack_bf2(f0 - f0h, f1 - f1h);
}
__device__ __forceinline__ uint32_t pack_h2(float f0, float f1) {
    uint32_t d;
    asm("cvt.rn.f16x2.f32 %0, %1, %2;" : "=r"(d) : "f"(f1), "f"(f0));
    return d;
}
__device__ __forceinline__ void mma_bf16(float& c0, float& c1, float& c2, float& c3,
                                         uint32_t a0, uint32_t a1, uint32_t a2, uint32_t a3,
                                         uint32_t b0, uint32_t b1) {
    asm volatile(
        "mma.sync.aligned.m16n8k16.row.col.f32.bf16.bf16.f32 "
        "{%0,%1,%2,%3}, {%4,%5,%6,%7}, {%8,%9}, {%0,%1,%2,%3};"
        : "+f"(c0), "+f"(c1), "+f"(c2), "+f"(c3)
        : "r"(a0), "r"(a1), "r"(a2), "r"(a3), "r"(b0), "r"(b1));
}
__device__ __forceinline__ void mma_f16(float& c0, float& c1, float& c2, float& c3,
                                        uint32_t a0, uint32_t a1, uint32_t a2, uint32_t a3,
                                        uint32_t b0, uint32_t b1) {
    asm volatile(
        "mma.sync.aligned.m16n8k16.row.col.f32.f16.f16.f32 "
        "{%0,%1,%2,%3}, {%4,%5,%6,%7}, {%8,%9}, {%0,%1,%2,%3};"
        : "+f"(c0), "+f"(c1), "+f"(c2), "+f"(c3)
        : "r"(a0), "r"(a1), "r"(a2), "r"(a3), "r"(b0), "r"(b1));
}

// ===========================================================================
// K1: xp[row][n] = sum_d x[row][d]*W_in[n][d]
// SINGLE-TERM fp16 mma (rel err ~4e-4), double-buffered.
// CTA 128 rows x 32 n, 256 thr. Warp w: rows (w&3)*32..+32, cols (w>>2)*16..+16.
// K=1024 in 32 chunks of 32, 1 sync/chunk.
// ===========================================================================
#define K1_A_U32 (128 * RSTR)             // 2560
#define K1_B_U32 (32 * RSTR)              // 640
#define K1_STAGE (K1_A_U32 + K1_B_U32)    // 3200 u32
#define K1_SMEM_BYTES (2 * K1_STAGE * 4)  // 25.6 KB

__global__ void __launch_bounds__(256) proj_mma_kernel(const float* __restrict__ x,
                                                       const float* __restrict__ W_in)
{
    extern __shared__ uint32_t sm1[];
    const int tid = threadIdx.x;
    const int wid = tid >> 5;
    const int lid = tid & 31;
    const int g   = lid >> 2;
    const int tig = lid & 3;
    const int row0 = blockIdx.x * 128;

    const int mroww = (wid & 3) * 32;
    const int ncolw = (wid >> 2) * 16;

    float4 pa[4];
    float4 pb;

    auto ldg_chunk = [&](int c) {
#pragma unroll
        for (int p = 0; p < 4; p++) {
            const int f = tid + p * 256;
            pa[p] = *(const float4*)(x + (size_t)(row0 + (f >> 3)) * D_MODEL +
                                     c * 32 + (f & 7) * 4);
        }
        pb = *(const float4*)(W_in + (size_t)(tid >> 3) * D_MODEL + c * 32 + (tid & 7) * 4);
    };
    auto sts_chunk = [&](int buf) {
        uint32_t* AB = sm1 + buf * K1_STAGE;
        uint32_t* BB = AB + K1_A_U32;
#pragma unroll
        for (int p = 0; p < 4; p++) {
            const int f = tid + p * 256;
            const int r = f >> 3, q = f & 7;
            *(uint2*)&AB[r * RSTR + q * 2] =
                make_uint2(pack_h2(pa[p].x, pa[p].y), pack_h2(pa[p].z, pa[p].w));
        }
        const int n = tid >> 3, q = tid & 7;
        *(uint2*)&BB[n * RSTR + q * 2] =
            make_uint2(pack_h2(pb.x, pb.y), pack_h2(pb.z, pb.w));
    };

    ldg_chunk(0);
    sts_chunk(0);
    ldg_chunk(1);
    __syncthreads();

    float acc[2][2][4];
#pragma unroll
    for (int mt = 0; mt < 2; mt++)
#pragma unroll
        for (int nt = 0; nt < 2; nt++)
#pragma unroll
            for (int i = 0; i < 4; i++) acc[mt][nt][i] = 0.f;

#pragma unroll 1
    for (int c = 0; c < 32; c++) {
        if (c + 1 < 32) sts_chunk((c + 1) & 1);
        if (c + 2 < 32) ldg_chunk(c + 2);

        const uint32_t* AB = sm1 + (c & 1) * K1_STAGE;
        const uint32_t* BB = AB + K1_A_U32;

#pragma unroll
        for (int ks = 0; ks < 2; ks++) {
            const int e0 = ks * 8 + tig;
            uint32_t ah[2][4];
#pragma unroll
            for (int mt = 0; mt < 2; mt++) {
                const int r = mroww + mt * 16 + g;
                ah[mt][0] = AB[r * RSTR + e0];
                ah[mt][1] = AB[(r + 8) * RSTR + e0];
                ah[mt][2] = AB[r * RSTR + e0 + 4];
                ah[mt][3] = AB[(r + 8) * RSTR + e0 + 4];
            }
            uint32_t bh_[2][2];
#pragma unroll
            for (int nt = 0; nt < 2; nt++) {
                const int n = ncolw + nt * 8 + g;
                bh_[nt][0] = BB[n * RSTR + e0];
                bh_[nt][1] = BB[n * RSTR + e0 + 4];
            }
#pragma unroll
            for (int mt = 0; mt < 2; mt++)
#pragma unroll
                for (int nt = 0; nt < 2; nt++) {
                    float* cc = acc[mt][nt];
                    mma_f16(cc[0], cc[1], cc[2], cc[3],
                            ah[mt][0], ah[mt][1], ah[mt][2], ah[mt][3],
                            bh_[nt][0], bh_[nt][1]);
                }
        }
        __syncthreads();
    }

#pragma unroll
    for (int mt = 0; mt < 2; mt++) {
        const int r0 = row0 + mroww + mt * 16 + g;
#pragma unroll
        for (int nt = 0; nt < 2; nt++) {
            const int col = ncolw + nt * 8 + tig * 2;
            *(float2*)(g_xp + (size_t)r0 * HALF + col) =
                make_float2(acc[mt][nt][0], acc[mt][nt][1]);
            *(float2*)(g_xp + (size_t)(r0 + 8) * HALF + col) =
                make_float2(acc[mt][nt][2], acc[mt][nt][3]);
        }
    }
}

// ===========================================================================
// K2: FIR taps + causal conv; writes y as interleaved (hi,lo) uint2  (R8)
// ===========================================================================
__global__ void __launch_bounds__(256) conv_kernel(
    const float* __restrict__ log_tau, const float* __restrict__ freq,
    const float* __restrict__ Bp,      const float* __restrict__ Cp,
    const float* __restrict__ log_dt)
{
    __shared__ float xp_s[(TT + TAPS - 1) * 32];   // 95 rows
    __shared__ float kk[TAPS][32];
    __shared__ float y_s[TT][32];
    __shared__ float pg[32], pl[32], pa[32];

    const int tid = threadIdx.x;
    const int blk = blockIdx.x;
    const int b   = blk >> 7;
    const int t0  = (blk & 127) * TT;

    if (tid < 32) {
        float dt  = expf(log_dt[0]);
        float tau = fmaxf(expf(log_tau[tid]), 1e-4f);
        pl[tid] = -tau * dt;
        pa[tid] = freq[tid] * dt;
        pg[tid] = logf(fabsf(Bp[tid]) + 1e-9f) + logf(fabsf(Cp[tid]) + 1e-9f);
    }

    for (int idx = tid; idx < (TT + TAPS - 1) * 32; idx += 256) {
        const int j = idx >> 5, n = idx & 31;
        const int tq = t0 - (TAPS - 1) + j;
        xp_s[idx] = (tq >= 0) ? g_xp[((size_t)b * T_LEN + tq) * HALF + n] : 0.f;
    }
    __syncthreads();

    for (int idx = tid; idx < TAPS * 32; idx += 256) {
        const int s = idx >> 5, n = idx & 31;
        kk[s][n] = expf(pg[n] + (float)s * pl[n]) * cosf((float)s * pa[n]);
    }
    __syncthreads();

    {
        const int n  = tid & 31;
        const int tg = tid >> 5;
#pragma unroll
        for (int r = 0; r < 8; r++) {
            const int tl = tg * 8 + r;
            float acc = 0.f;
            const float* base = &xp_s[(tl + TAPS - 1) * 32 + n];
#pragma unroll
            for (int s = 0; s < TAPS; s++) {
                acc += kk[s][n] * base[-s * 32];
            }
            y_s[tl][n] = acc;
        }
    }
    __syncthreads();

    for (int idx = tid; idx < TT * 16; idx += 256) {
        const int t = idx >> 4, kp = idx & 15;
        uint32_t h, l;
        split_bf2(y_s[t][2 * kp], y_s[t][2 * kp + 1], h, l);
        g_y[((size_t)b * T_LEN + t0 + t) * 16 + kp] = make_uint2(h, l);
    }
}

// ===========================================================================
// K3: GEMM2  out[t][d] = sum_n y[t][n] * W_out[d][n]  (R8: bf16x3, d=256 tile)
// ===========================================================================
#define K3_A_U32      (128 * RSTR2)          // 5120
#define K3_B_U32      (256 * RSTR2)          // 10240
#define K3_SMEM_BYTES ((K3_A_U32 + K3_B_U32) * 4)   // 61440

__global__ void __launch_bounds__(256) gemm2_kernel(const float* __restrict__ W_out,
                                                    float* __restrict__ out)
{
    extern __shared__ uint32_t sm3[];
    uint32_t* As = sm3;
    uint32_t* Bs = sm3 + K3_A_U32;

    const int tid = threadIdx.x;
    const int wid = tid >> 5;
    const int lid = tid & 31;
    const int g   = lid >> 2;
    const int tig = lid & 3;

    const int t0 = blockIdx.x * 128;
    const int d0 = blockIdx.y * 256;

#pragma unroll
    for (int p = 0; p < 4; p++) {
        const int f = tid + p * 256;
        const int r = f >> 3, j = f & 7;
        uint4 v = *(const uint4*)&g_y[(size_t)(t0 + r) * 16 + j * 2];
        *(uint4*)&As[r * RSTR2 + j * 4] = v;
    }
#pragma unroll
    for (int p = 0; p < 8; p++) {
        const int f = tid + p * 256;
        const int r = f >> 3, q = f & 7;
        float4 v = *(const float4*)(W_out + (size_t)(d0 + r) * HALF + q * 4);
        uint32_t h0, l0, h1, l1;
        split_bf2(v.x, v.y, h0, l0);
        split_bf2(v.z, v.w, h1, l1);
        *(uint4*)&Bs[r * RSTR2 + q * 4] = make_uint4(h0, l0, h1, l1);
    }
    __syncthreads();

    const int mg = wid & 3;
    const int dg = wid >> 2;

    uint32_t afh[2][2][4], afl[2][2][4];
#pragma unroll
    for (int mt = 0; mt < 2; mt++) {
        const int r = mg * 32 + mt * 16 + g;
#pragma unroll
        for (int ks = 0; ks < 2; ks++) {
            const int e0 = ks * 8 + tig;
            uint2 a00 = *(const uint2*)&As[r * RSTR2 + e0 * 2];
            uint2 a10 = *(const uint2*)&As[(r + 8) * RSTR2 + e0 * 2];
            uint2 a01 = *(const uint2*)&As[r * RSTR2 + (e0 + 4) * 2];
            uint2 a11 = *(const uint2*)&As[(r + 8) * RSTR2 + (e0 + 4) * 2];
            afh[mt][ks][0] = a00.x; afl[mt][ks][0] = a00.y;
            afh[mt][ks][1] = a10.x; afl[mt][ks][1] = a10.y;
            afh[mt][ks][2] = a01.x; afl[mt][ks][2] = a01.y;
            afh[mt][ks][3] = a11.x; afl[mt][ks][3] = a11.y;
        }
    }

#pragma unroll 1
    for (int ch = 0; ch < 16; ch++) {
        const int nb = dg * 128 + ch * 8;
        float acc[2][4];
#pragma unroll
        for (int mt = 0; mt < 2; mt++)
#pragma unroll
            for (int i = 0; i < 4; i++) acc[mt][i] = 0.f;

#pragma unroll
        for (int ks = 0; ks < 2; ks++) {
            const int e0 = ks * 8 + tig;
            const int nr = nb + g;
            uint2 b0 = *(const uint2*)&Bs[nr * RSTR2 + e0 * 2];
            uint2 b1 = *(const uint2*)&Bs[nr * RSTR2 + (e0 + 4) * 2];
            uint32_t bh0 = b0.x, bl0 = b0.y;
            uint32_t bh1 = b1.x, bl1 = b1.y;
#pragma unroll
            for (int mt = 0; mt < 2; mt++) {
                float* cc = acc[mt];
                mma_bf16(cc[0], cc[1], cc[2], cc[3],
                         afh[mt][ks][0], afh[mt][ks][1], afh[mt][ks][2], afh[mt][ks][3],
                         bh0, bh1);
                mma_bf16(cc[0], cc[1], cc[2], cc[3],
                         afh[mt][ks][0], afh[mt][ks][1], afh[mt][ks][2], afh[mt][ks][3],
                         bl0, bl1);
                mma_bf16(cc[0], cc[1], cc[2], cc[3],
                         afl[mt][ks][0], afl[mt][ks][1], afl[mt][ks][2], afl[mt][ks][3],
                         bh0, bh1);
            }
        }

        const int col = d0 + nb + tig * 2;
#pragma unroll
        for (int mt = 0; mt < 2; mt++) {
            const int tr = t0 + mg * 32 + mt * 16 + g;
            *(float2*)(out + (size_t)tr * D_MODEL + col) =
                make_float2(acc[mt][0], acc[mt][1]);
            *(float2*)(out + (size_t)(tr + 8) * D_MODEL + col) =
                make_float2(acc[mt][2], acc[mt][3]);
        }
    }
}

// ---------------------------------------------------------------------------
extern "C" void kernel_launch(void* const* d_in, const int* in_sizes, int n_in,
                              void* d_out, int out_size)
{
    const float* x       = (const float*)d_in[0];
    const float* log_tau = (const float*)d_in[1];
    const float* freq    = (const float*)d_in[2];
    const float* Bp      = (const float*)d_in[3];
    const float* Cp      = (const float*)d_in[4];
    const float* log_dt  = (const float*)d_in[5];
    const float* W_in    = (const float*)d_in[6];
    const float* W_out   = (const float*)d_in[7];
    float* out           = (float*)d_out;

    (void)in_sizes; (void)n_in; (void)out_size;

    static bool attr_set = false;
    if (!attr_set) {
        cudaFuncSetAttribute(proj_mma_kernel,
                             cudaFuncAttributeMaxDynamicSharedMemorySize, K1_SMEM_BYTES);
        cudaFuncSetAttribute(gemm2_kernel,
                             cudaFuncAttributeMaxDynamicSharedMemorySize, K3_SMEM_BYTES);
        attr_set = true;
    }

    proj_mma_kernel<<<ROWS / 128, 256, K1_SMEM_BYTES>>>(x, W_in);
    conv_kernel<<<(BATCH * T_LEN) / TT, 256>>>(log_tau, freq, Bp, Cp, log_dt);
    gemm2_kernel<<<dim3(ROWS / 128, D_MODEL / 256), 256, K3_SMEM_BYTES>>>(W_out, out);
}

// round 13
// speedup vs baseline: 1.4471x; 1.0293x over previous
#include <cuda_runtime.h>
#include <cstdint>

#define D_MODEL 1024
#define HALF    32
#define T_LEN   8192
#define BATCH   4
#define ROWS    (BATCH * T_LEN)   // 32768
#define TAPS    32
#define TT      64
#define RSTR    20   // u32 stride: 16 data + 4 pad (conflict-free)

// scratch: projected modes xp[row][n] fp32 (4 MB)
__device__ float g_xp[ROWS * HALF];
// conv output: 16 fp16x2 pairs per row (2 MB)
__device__ uint32_t g_y[ROWS * 16];

// ---------------------------------------------------------------------------
// pack helpers
// ---------------------------------------------------------------------------
__device__ __forceinline__ uint32_t pack_h2(float f0, float f1) {
    uint32_t d;
    asm("cvt.rn.f16x2.f32 %0, %1, %2;" : "=r"(d) : "f"(f1), "f"(f0));
    return d;
}
__device__ __forceinline__ void mma_f16(float& c0, float& c1, float& c2, float& c3,
                                        uint32_t a0, uint32_t a1, uint32_t a2, uint32_t a3,
                                        uint32_t b0, uint32_t b1) {
    asm volatile(
        "mma.sync.aligned.m16n8k16.row.col.f32.f16.f16.f32 "
        "{%0,%1,%2,%3}, {%4,%5,%6,%7}, {%8,%9}, {%0,%1,%2,%3};"
        : "+f"(c0), "+f"(c1), "+f"(c2), "+f"(c3)
        : "r"(a0), "r"(a1), "r"(a2), "r"(a3), "r"(b0), "r"(b1));
}

// ===========================================================================
// K1: xp[row][n] = sum_d x[row][d]*W_in[n][d]
// SINGLE-TERM fp16 mma, double-buffered.  (R12, unchanged — proven 33.8 us)
// ===========================================================================
#define K1_A_U32 (128 * RSTR)             // 2560
#define K1_B_U32 (32 * RSTR)              // 640
#define K1_STAGE (K1_A_U32 + K1_B_U32)    // 3200 u32
#define K1_SMEM_BYTES (2 * K1_STAGE * 4)  // 25.6 KB

__global__ void __launch_bounds__(256) proj_mma_kernel(const float* __restrict__ x,
                                                       const float* __restrict__ W_in)
{
    extern __shared__ uint32_t sm1[];
    const int tid = threadIdx.x;
    const int wid = tid >> 5;
    const int lid = tid & 31;
    const int g   = lid >> 2;
    const int tig = lid & 3;
    const int row0 = blockIdx.x * 128;

    const int mroww = (wid & 3) * 32;
    const int ncolw = (wid >> 2) * 16;

    float4 pa[4];
    float4 pb;

    auto ldg_chunk = [&](int c) {
#pragma unroll
        for (int p = 0; p < 4; p++) {
            const int f = tid + p * 256;
            pa[p] = *(const float4*)(x + (size_t)(row0 + (f >> 3)) * D_MODEL +
                                     c * 32 + (f & 7) * 4);
        }
        pb = *(const float4*)(W_in + (size_t)(tid >> 3) * D_MODEL + c * 32 + (tid & 7) * 4);
    };
    auto sts_chunk = [&](int buf) {
        uint32_t* AB = sm1 + buf * K1_STAGE;
        uint32_t* BB = AB + K1_A_U32;
#pragma unroll
        for (int p = 0; p < 4; p++) {
            const int f = tid + p * 256;
            const int r = f >> 3, q = f & 7;
            *(uint2*)&AB[r * RSTR + q * 2] =
                make_uint2(pack_h2(pa[p].x, pa[p].y), pack_h2(pa[p].z, pa[p].w));
        }
        const int n = tid >> 3, q = tid & 7;
        *(uint2*)&BB[n * RSTR + q * 2] =
            make_uint2(pack_h2(pb.x, pb.y), pack_h2(pb.z, pb.w));
    };

    ldg_chunk(0);
    sts_chunk(0);
    ldg_chunk(1);
    __syncthreads();

    float acc[2][2][4];
#pragma unroll
    for (int mt = 0; mt < 2; mt++)
#pragma unroll
        for (int nt = 0; nt < 2; nt++)
#pragma unroll
            for (int i = 0; i < 4; i++) acc[mt][nt][i] = 0.f;

#pragma unroll 1
    for (int c = 0; c < 32; c++) {
        if (c + 1 < 32) sts_chunk((c + 1) & 1);
        if (c + 2 < 32) ldg_chunk(c + 2);

        const uint32_t* AB = sm1 + (c & 1) * K1_STAGE;
        const uint32_t* BB = AB + K1_A_U32;

#pragma unroll
        for (int ks = 0; ks < 2; ks++) {
            const int e0 = ks * 8 + tig;
            uint32_t ah[2][4];
#pragma unroll
            for (int mt = 0; mt < 2; mt++) {
                const int r = mroww + mt * 16 + g;
                ah[mt][0] = AB[r * RSTR + e0];
                ah[mt][1] = AB[(r + 8) * RSTR + e0];
                ah[mt][2] = AB[r * RSTR + e0 + 4];
                ah[mt][3] = AB[(r + 8) * RSTR + e0 + 4];
            }
            uint32_t bh_[2][2];
#pragma unroll
            for (int nt = 0; nt < 2; nt++) {
                const int n = ncolw + nt * 8 + g;
                bh_[nt][0] = BB[n * RSTR + e0];
                bh_[nt][1] = BB[n * RSTR + e0 + 4];
            }
#pragma unroll
            for (int mt = 0; mt < 2; mt++)
#pragma unroll
                for (int nt = 0; nt < 2; nt++) {
                    float* cc = acc[mt][nt];
                    mma_f16(cc[0], cc[1], cc[2], cc[3],
                            ah[mt][0], ah[mt][1], ah[mt][2], ah[mt][3],
                            bh_[nt][0], bh_[nt][1]);
                }
        }
        __syncthreads();
    }

#pragma unroll
    for (int mt = 0; mt < 2; mt++) {
        const int r0 = row0 + mroww + mt * 16 + g;
#pragma unroll
        for (int nt = 0; nt < 2; nt++) {
            const int col = ncolw + nt * 8 + tig * 2;
            *(float2*)(g_xp + (size_t)r0 * HALF + col) =
                make_float2(acc[mt][nt][0], acc[mt][nt][1]);
            *(float2*)(g_xp + (size_t)(r0 + 8) * HALF + col) =
                make_float2(acc[mt][nt][2], acc[mt][nt][3]);
        }
    }
}

// ===========================================================================
// K2: FIR taps + causal conv; writes y as fp16x2 pairs (single precision term)
// ===========================================================================
__global__ void __launch_bounds__(256) conv_kernel(
    const float* __restrict__ log_tau, const float* __restrict__ freq,
    const float* __restrict__ Bp,      const float* __restrict__ Cp,
    const float* __restrict__ log_dt)
{
    __shared__ float xp_s[(TT + TAPS - 1) * 32];   // 95 rows
    __shared__ float kk[TAPS][32];
    __shared__ float y_s[TT][32];
    __shared__ float pg[32], pl[32], pa[32];

    const int tid = threadIdx.x;
    const int blk = blockIdx.x;
    const int b   = blk >> 7;
    const int t0  = (blk & 127) * TT;

    if (tid < 32) {
        float dt  = expf(log_dt[0]);
        float tau = fmaxf(expf(log_tau[tid]), 1e-4f);
        pl[tid] = -tau * dt;
        pa[tid] = freq[tid] * dt;
        pg[tid] = logf(fabsf(Bp[tid]) + 1e-9f) + logf(fabsf(Cp[tid]) + 1e-9f);
    }

    for (int idx = tid; idx < (TT + TAPS - 1) * 32; idx += 256) {
        const int j = idx >> 5, n = idx & 31;
        const int tq = t0 - (TAPS - 1) + j;
        xp_s[idx] = (tq >= 0) ? g_xp[((size_t)b * T_LEN + tq) * HALF + n] : 0.f;
    }
    __syncthreads();

    for (int idx = tid; idx < TAPS * 32; idx += 256) {
        const int s = idx >> 5, n = idx & 31;
        kk[s][n] = expf(pg[n] + (float)s * pl[n]) * cosf((float)s * pa[n]);
    }
    __syncthreads();

    {
        const int n  = tid & 31;
        const int tg = tid >> 5;
#pragma unroll
        for (int r = 0; r < 8; r++) {
            const int tl = tg * 8 + r;
            float acc = 0.f;
            const float* base = &xp_s[(tl + TAPS - 1) * 32 + n];
#pragma unroll
            for (int s = 0; s < TAPS; s++) {
                acc += kk[s][n] * base[-s * 32];
            }
            y_s[tl][n] = acc;
        }
    }
    __syncthreads();

    for (int idx = tid; idx < TT * 16; idx += 256) {
        const int t = idx >> 4, kp = idx & 15;
        g_y[((size_t)b * T_LEN + t0 + t) * 16 + kp] =
            pack_h2(y_s[t][2 * kp], y_s[t][2 * kp + 1]);
    }
}

// ===========================================================================
// K3: GEMM2  out[t][d] = sum_n y[t][n] * W_out[d][n]
// SINGLE-TERM fp16 mma. CTA 128 t x 256 d, 256 thr. grid (256, 4). smem 30 KB.
// ===========================================================================
#define K3_A_U32      (128 * RSTR)           // 2560
#define K3_B_U32      (256 * RSTR)           // 5120
#define K3_SMEM_BYTES ((K3_A_U32 + K3_B_U32) * 4)   // 30720

__global__ void __launch_bounds__(256) gemm2_kernel(const float* __restrict__ W_out,
                                                    float* __restrict__ out)
{
    extern __shared__ uint32_t sm3[];
    uint32_t* As = sm3;
    uint32_t* Bs = sm3 + K3_A_U32;

    const int tid = threadIdx.x;
    const int wid = tid >> 5;
    const int lid = tid & 31;
    const int g   = lid >> 2;
    const int tig = lid & 3;

    const int t0 = blockIdx.x * 128;
    const int d0 = blockIdx.y * 256;

    // stage A: 128 rows x 16 u32 = 512 uint4
#pragma unroll
    for (int p = 0; p < 2; p++) {
        const int f = tid + p * 256;
        const int r = f >> 2, j = f & 3;
        uint4 v = *(const uint4*)&g_y[(size_t)(t0 + r) * 16 + j * 4];
        *(uint4*)&As[r * RSTR + j * 4] = v;
    }
    // stage B: W_out 256 rows x 32 fp32 -> fp16 pack (8 float4/thr)
#pragma unroll
    for (int p = 0; p < 8; p++) {
        const int f = tid + p * 256;
        const int r = f >> 3, q = f & 7;
        float4 v = *(const float4*)(W_out + (size_t)(d0 + r) * HALF + q * 4);
        *(uint2*)&Bs[r * RSTR + q * 2] =
            make_uint2(pack_h2(v.x, v.y), pack_h2(v.z, v.w));
    }
    __syncthreads();

    const int mg = wid & 3;
    const int dg = wid >> 2;

    uint32_t af[2][2][4];
#pragma unroll
    for (int mt = 0; mt < 2; mt++) {
        const int r = mg * 32 + mt * 16 + g;
#pragma unroll
        for (int ks = 0; ks < 2; ks++) {
            const int e0 = ks * 8 + tig;
            af[mt][ks][0] = As[r * RSTR + e0];
            af[mt][ks][1] = As[(r + 8) * RSTR + e0];
            af[mt][ks][2] = As[r * RSTR + e0 + 4];
            af[mt][ks][3] = As[(r + 8) * RSTR + e0 + 4];
        }
    }

#pragma unroll 1
    for (int ch = 0; ch < 16; ch++) {
        const int nb = dg * 128 + ch * 8;
        float acc[2][4];
#pragma unroll
        for (int mt = 0; mt < 2; mt++)
#pragma unroll
            for (int i = 0; i < 4; i++) acc[mt][i] = 0.f;

#pragma unroll
        for (int ks = 0; ks < 2; ks++) {
            const int e0 = ks * 8 + tig;
            const int nr = nb + g;
            uint32_t b0 = Bs[nr * RSTR + e0];
            uint32_t b1 = Bs[nr * RSTR + e0 + 4];
#pragma unroll
            for (int mt = 0; mt < 2; mt++) {
                float* cc = acc[mt];
                mma_f16(cc[0], cc[1], cc[2], cc[3],
                        af[mt][ks][0], af[mt][ks][1], af[mt][ks][2], af[mt][ks][3],
                        b0, b1);
            }
        }

        const int col = d0 + nb + tig * 2;
#pragma unroll
        for (int mt = 0; mt < 2; mt++) {
            const int tr = t0 + mg * 32 + mt * 16 + g;
            *(float2*)(out + (size_t)tr * D_MODEL + col) =
                make_float2(acc[mt][0], acc[mt][1]);
            *(float2*)(out + (size_t)(tr + 8) * D_MODEL + col) =
                make_float2(acc[mt][2], acc[mt][3]);
        }
    }
}

// ---------------------------------------------------------------------------
extern "C" void kernel_launch(void* const* d_in, const int* in_sizes, int n_in,
                              void* d_out, int out_size)
{
    const float* x       = (const float*)d_in[0];
    const float* log_tau = (const float*)d_in[1];
    const float* freq    = (const float*)d_in[2];
    const float* Bp      = (const float*)d_in[3];
    const float* Cp      = (const float*)d_in[4];
    const float* log_dt  = (const float*)d_in[5];
    const float* W_in    = (const float*)d_in[6];
    const float* W_out   = (const float*)d_in[7];
    float* out           = (float*)d_out;

    (void)in_sizes; (void)n_in; (void)out_size;

    static bool attr_set = false;
    if (!attr_set) {
        cudaFuncSetAttribute(proj_mma_kernel,
                             cudaFuncAttributeMaxDynamicSharedMemorySize, K1_SMEM_BYTES);
        cudaFuncSetAttribute(gemm2_kernel,
                             cudaFuncAttributeMaxDynamicSharedMemorySize, K3_SMEM_BYTES);
        attr_set = true;
    }

    proj_mma_kernel<<<ROWS / 128, 256, K1_SMEM_BYTES>>>(x, W_in);
    conv_kernel<<<(BATCH * T_LEN) / TT, 256>>>(log_tau, freq, Bp, Cp, log_dt);
    gemm2_kernel<<<dim3(ROWS / 128, D_MODEL / 256), 256, K3_SMEM_BYTES>>>(W_out, out);
}